// round 8
// baseline (speedup 1.0000x reference)
#include <cuda_runtime.h>
#include <cstdint>

// ---------------- static scratch (device globals: allocation-free) ----------------
#define NMAX 100000
#define EMAX 1600000
#define HDIM 64

__device__ float g_deg[NMAX];
__device__ float g_dis[NMAX];
__device__ int   g_src[EMAX];
__device__ int   g_tgt[EMAX];
__device__ int   g_rowcnt[NMAX];
__device__ int   g_rowptr[NMAX + 1];
__device__ int   g_cursor[NMAX];
__device__ int2  g_epay[EMAX];          // {src, bits(wn)} sorted by tgt
__device__ float g_bufA[(size_t)NMAX * HDIM];
__device__ float g_bufB[(size_t)NMAX * HDIM];
__device__ float g_tx1[(size_t)NMAX * HDIM];
__device__ float g_tmp[(size_t)NMAX * HDIM];
__device__ float g_weff[4 * 192 * 64];
__device__ float g_sums[64];
__device__ float g_cnt[64];

// ---------------- utility ----------------
__global__ void init_counts_kernel(int n) {
    int i = blockIdx.x * blockDim.x + threadIdx.x;
    if (i < n) { g_deg[i] = 0.f; g_rowcnt[i] = 0; }
}

__global__ void zero_pool_kernel() {
    int i = threadIdx.x;
    if (i < 64) g_sums[i] = 0.f;
    else if (i < 128) g_cnt[i - 64] = 0.f;
}

// ---------------- preprocessing ----------------
// edge_index is int32 (JAX default x64-disabled downcasts the reference's int64).
__global__ void edge_prep_kernel(const int* __restrict__ ei,
                                 const float* __restrict__ ew, int E, int N) {
    int e = blockIdx.x * blockDim.x + threadIdx.x;
    if (e >= E) return;
    int s = ei[e];
    int t = ei[(size_t)E + e];
    if ((unsigned)s >= (unsigned)N) s = 0;   // harden against dtype surprises
    if ((unsigned)t >= (unsigned)N) t = 0;
    g_src[e] = s;
    g_tgt[e] = t;
    atomicAdd(&g_deg[s], ew[e]);
    atomicAdd(&g_rowcnt[t], 1);
}

__global__ void dis_kernel(int n) {
    int i = blockIdx.x * blockDim.x + threadIdx.x;
    if (i >= n) return;
    float d = g_deg[i];
    g_dis[i] = (d > 0.f) ? rsqrtf(d) : 0.f;
}

// single-block exclusive scan of g_rowcnt -> g_rowptr (+ copy to g_cursor)
__global__ void scan_kernel(int N) {
    __shared__ int warp_sums[32];
    __shared__ int s_carry;
    int tid = threadIdx.x, lane = tid & 31, wid = tid >> 5;
    if (tid == 0) s_carry = 0;
    __syncthreads();
    for (int base = 0; base < N; base += 1024) {
        int i = base + tid;
        int v = (i < N) ? g_rowcnt[i] : 0;
        int s = v;
#pragma unroll
        for (int o = 1; o < 32; o <<= 1) {
            int u = __shfl_up_sync(0xffffffffu, s, o);
            if (lane >= o) s += u;
        }
        if (lane == 31) warp_sums[wid] = s;
        __syncthreads();
        if (tid < 32) {
            int s2 = warp_sums[tid];
#pragma unroll
            for (int o = 1; o < 32; o <<= 1) {
                int u = __shfl_up_sync(0xffffffffu, s2, o);
                if (tid >= o) s2 += u;
            }
            warp_sums[tid] = s2;
        }
        __syncthreads();
        int prev = (wid ? warp_sums[wid - 1] : 0);
        int excl = s_carry + prev + (s - v);
        if (i < N) { g_rowptr[i] = excl; g_cursor[i] = excl; }
        int block_total = warp_sums[31];
        __syncthreads();
        if (tid == 0) s_carry += block_total;
        __syncthreads();
    }
    if (tid == 0) g_rowptr[N] = s_carry;
}

// scatter edges into CSR slots; fuse wn computation
__global__ void fill_kernel(const float* __restrict__ ew, int E) {
    int e = blockIdx.x * blockDim.x + threadIdx.x;
    if (e >= E) return;
    int s = g_src[e];
    int t = g_tgt[e];
    float wn = -g_dis[s] * ew[e] * g_dis[t];
    int pos = atomicAdd(&g_cursor[t], 1);
    g_epay[pos] = make_int2(s, __float_as_int(wn));
}

// Weff[l][kk][o]: kk<64 -> W0-W2 ; 64..127 -> W1 ; 128..191 -> 2*W2
__global__ void weff_kernel(const float* __restrict__ w) {
    int idx = blockIdx.x * blockDim.x + threadIdx.x;
    if (idx >= 4 * 192 * 64) return;
    int o  = idx & 63;
    int kk = (idx >> 6) % 192;
    int l  = idx / (192 * 64);
    const float* wl = w + (size_t)l * 3 * 4096;
    float v;
    if (kk < 64)       v = wl[kk * 64 + o] - wl[2 * 4096 + kk * 64 + o];
    else if (kk < 128) v = wl[4096 + (kk - 64) * 64 + o];
    else               v = 2.f * wl[2 * 4096 + (kk - 128) * 64 + o];
    g_weff[idx] = v;
}

// ---------------- CSR propagation: out[t] = sum_{e: tgt==t} wn_e * h[src_e] ----------------
// 8 lanes per node; lane owns 32B (2 float4) of the 256B feature row. No atomics, no pre-zero.
__global__ void prop_csr_kernel(const float* __restrict__ h, float* __restrict__ out, int n) {
    int gid = blockIdx.x * blockDim.x + threadIdx.x;
    int node = gid >> 3;
    if (node >= n) return;
    int lg = gid & 7;
    int beg = g_rowptr[node];
    int end = g_rowptr[node + 1];
    const float4* hp = reinterpret_cast<const float4*>(h);
    float4 a0 = make_float4(0.f, 0.f, 0.f, 0.f);
    float4 a1 = make_float4(0.f, 0.f, 0.f, 0.f);
    int j = beg;
    for (; j + 2 <= end; j += 2) {
        int2 p0 = g_epay[j];
        int2 p1 = g_epay[j + 1];
        float w0 = __int_as_float(p0.y);
        float w1 = __int_as_float(p1.y);
        const float4* r0 = hp + ((size_t)p0.x * 16 + lg * 2);
        const float4* r1 = hp + ((size_t)p1.x * 16 + lg * 2);
        float4 v00 = r0[0], v01 = r0[1];
        float4 v10 = r1[0], v11 = r1[1];
        a0.x += w0 * v00.x; a0.y += w0 * v00.y; a0.z += w0 * v00.z; a0.w += w0 * v00.w;
        a1.x += w0 * v01.x; a1.y += w0 * v01.y; a1.z += w0 * v01.z; a1.w += w0 * v01.w;
        a0.x += w1 * v10.x; a0.y += w1 * v10.y; a0.z += w1 * v10.z; a0.w += w1 * v10.w;
        a1.x += w1 * v11.x; a1.y += w1 * v11.y; a1.z += w1 * v11.z; a1.w += w1 * v11.w;
    }
    if (j < end) {
        int2 p0 = g_epay[j];
        float w0 = __int_as_float(p0.y);
        const float4* r0 = hp + ((size_t)p0.x * 16 + lg * 2);
        float4 v00 = r0[0], v01 = r0[1];
        a0.x += w0 * v00.x; a0.y += w0 * v00.y; a0.z += w0 * v00.z; a0.w += w0 * v00.w;
        a1.x += w0 * v01.x; a1.y += w0 * v01.y; a1.z += w0 * v01.z; a1.w += w0 * v01.w;
    }
    float4* op = reinterpret_cast<float4*>(out) + ((size_t)node * 16 + lg * 2);
    op[0] = a0;
    op[1] = a1;
}

// ---------------- fused layer GEMM: out = [p0|p1|p2] @ Weff + bias ----------------
__global__ void gemm_kernel(const float* __restrict__ p0, const float* __restrict__ p1,
                            const float* __restrict__ p2, const float* __restrict__ Weff,
                            const float* __restrict__ bias, float* __restrict__ out,
                            int n_nodes) {
    __shared__ float As[16][64];
    __shared__ float Bs[16][64];
    __shared__ float bsm[64];
    int tid = threadIdx.x;
    int m0 = blockIdx.x * 64;
    if (tid < 64) bsm[tid] = bias[tid];
    int ty = tid >> 4;
    int tx = tid & 15;
    float c[4][4];
#pragma unroll
    for (int i = 0; i < 4; i++)
#pragma unroll
        for (int j = 0; j < 4; j++) c[i][j] = 0.f;

    const float* parts[3] = {p0, p1, p2};

#pragma unroll 1
    for (int kt = 0; kt < 12; kt++) {
        int kg = kt * 16;
        const float* P = parts[kg >> 6];
        int ko = kg & 63;
        {
            int node_l = tid >> 2;
            int k4 = (tid & 3) << 2;
            float4 av = make_float4(0.f, 0.f, 0.f, 0.f);
            int node = m0 + node_l;
            if (node < n_nodes)
                av = *reinterpret_cast<const float4*>(P + (size_t)node * 64 + ko + k4);
            As[k4 + 0][node_l] = av.x;
            As[k4 + 1][node_l] = av.y;
            As[k4 + 2][node_l] = av.z;
            As[k4 + 3][node_l] = av.w;
        }
        {
            int kr = tid >> 4;
            int c4 = (tid & 15) << 2;
            float4 bv = *reinterpret_cast<const float4*>(Weff + (size_t)(kg + kr) * 64 + c4);
            *reinterpret_cast<float4*>(&Bs[kr][c4]) = bv;
        }
        __syncthreads();
#pragma unroll
        for (int k = 0; k < 16; k++) {
            float4 a = *reinterpret_cast<const float4*>(&As[k][ty << 2]);
            float4 b = *reinterpret_cast<const float4*>(&Bs[k][tx << 2]);
            c[0][0] += a.x * b.x; c[0][1] += a.x * b.y; c[0][2] += a.x * b.z; c[0][3] += a.x * b.w;
            c[1][0] += a.y * b.x; c[1][1] += a.y * b.y; c[1][2] += a.y * b.z; c[1][3] += a.y * b.w;
            c[2][0] += a.z * b.x; c[2][1] += a.z * b.y; c[2][2] += a.z * b.z; c[2][3] += a.z * b.w;
            c[3][0] += a.w * b.x; c[3][1] += a.w * b.y; c[3][2] += a.w * b.z; c[3][3] += a.w * b.w;
        }
        __syncthreads();
    }
#pragma unroll
    for (int i = 0; i < 4; i++) {
        int node = m0 + (ty << 2) + i;
        if (node < n_nodes) {
            float4 o;
            int n0 = tx << 2;
            o.x = c[i][0] + bsm[n0 + 0];
            o.y = c[i][1] + bsm[n0 + 1];
            o.z = c[i][2] + bsm[n0 + 2];
            o.w = c[i][3] + bsm[n0 + 3];
            *reinterpret_cast<float4*>(out + (size_t)node * 64 + n0) = o;
        }
    }
}

// ---------------- readout MLP (64->32 relu ->1) + scatter mean ----------------
__global__ void readout_kernel(const float* __restrict__ y, const int* __restrict__ batch,
                               const float* __restrict__ wr1, const float* __restrict__ br1,
                               const float* __restrict__ wr2, const float* __restrict__ br2,
                               int n, int G) {
    __shared__ float Wsm[64 * 32];
    __shared__ float w2sm[32];
    __shared__ float b1sm[32];
    for (int i = threadIdx.x; i < 64 * 32; i += blockDim.x) Wsm[i] = wr1[i];
    if (threadIdx.x < 32) {
        w2sm[threadIdx.x] = wr2[threadIdx.x];
        b1sm[threadIdx.x] = br1[threadIdx.x];
    }
    __syncthreads();
    float b2 = br2[0];
    int lane = threadIdx.x & 31;
    int warp = (blockIdx.x * blockDim.x + threadIdx.x) >> 5;
    int nwarps = (gridDim.x * blockDim.x) >> 5;
    for (int node = warp; node < n; node += nwarps) {
        float yv0 = y[(size_t)node * 64 + lane];
        float yv1 = y[(size_t)node * 64 + 32 + lane];
        float acc = b1sm[lane];
#pragma unroll
        for (int k = 0; k < 32; k++)
            acc += __shfl_sync(0xffffffffu, yv0, k) * Wsm[k * 32 + lane];
#pragma unroll
        for (int k = 0; k < 32; k++)
            acc += __shfl_sync(0xffffffffu, yv1, k) * Wsm[(32 + k) * 32 + lane];
        acc = fmaxf(acc, 0.f);
        float r = acc * w2sm[lane];
#pragma unroll
        for (int off = 16; off; off >>= 1)
            r += __shfl_xor_sync(0xffffffffu, r, off);
        if (lane == 0) {
            int g = batch[node];
            if ((unsigned)g < (unsigned)G) {
                atomicAdd(&g_sums[g], r + b2);
                atomicAdd(&g_cnt[g], 1.f);
            }
        }
    }
}

__global__ void finalize_kernel(float* __restrict__ out, int G) {
    int g = threadIdx.x;
    if (g < G) out[g] = g_sums[g] / fmaxf(g_cnt[g], 1.f);
}

// ---------------- host ----------------
extern "C" void kernel_launch(void* const* d_in, const int* in_sizes, int n_in,
                              void* d_out, int out_size) {
    const float* x        = (const float*)d_in[0];
    const int*   ei       = (const int*)d_in[1];     // int32 (JAX x64 disabled)
    const float* ew       = (const float*)d_in[2];
    const int*   batch    = (const int*)d_in[3];     // int32
    const float* w_layers = (const float*)d_in[4];
    const float* b_layers = (const float*)d_in[5];
    const float* wr1      = (const float*)d_in[6];
    const float* br1      = (const float*)d_in[7];
    const float* wr2      = (const float*)d_in[8];
    const float* br2      = (const float*)d_in[9];

    int N = in_sizes[0] / HDIM;
    int E = in_sizes[1] / 2;
    int G = out_size;

    float *bufA, *bufB, *tx1, *tmp, *weff;
    cudaGetSymbolAddress((void**)&bufA, g_bufA);
    cudaGetSymbolAddress((void**)&bufB, g_bufB);
    cudaGetSymbolAddress((void**)&tx1,  g_tx1);
    cudaGetSymbolAddress((void**)&tmp,  g_tmp);
    cudaGetSymbolAddress((void**)&weff, g_weff);

    const int TPB = 256;

    // preprocessing: degrees + CSR by target
    init_counts_kernel<<<(N + TPB - 1) / TPB, TPB>>>(N);
    edge_prep_kernel<<<(E + TPB - 1) / TPB, TPB>>>(ei, ew, E, N);
    dis_kernel<<<(N + TPB - 1) / TPB, TPB>>>(N);
    scan_kernel<<<1, 1024>>>(N);
    fill_kernel<<<(E + TPB - 1) / TPB, TPB>>>(ew, E);
    weff_kernel<<<(4 * 192 * 64 + TPB - 1) / TPB, TPB>>>(w_layers);

    int pgrid = (N * 8 + TPB - 1) / TPB;
    int ggrid = (N + 63) / 64;

    const float* ycur = x;
    float* bufs[2] = {bufA, bufB};
    for (int l = 0; l < 4; l++) {
        prop_csr_kernel<<<pgrid, TPB>>>(ycur, tx1, N);
        prop_csr_kernel<<<pgrid, TPB>>>(tx1, tmp, N);
        gemm_kernel<<<ggrid, TPB>>>(ycur, tx1, tmp,
                                    weff + (size_t)l * 192 * 64,
                                    b_layers + (size_t)l * 64,
                                    bufs[l & 1], N);
        ycur = bufs[l & 1];
    }

    // readout + pooling
    zero_pool_kernel<<<1, 128>>>();
    readout_kernel<<<256, TPB>>>(ycur, batch, wr1, br1, wr2, br2, N, G);
    finalize_kernel<<<1, 64>>>((float*)d_out, G);
}

// round 9
// speedup vs baseline: 1.5096x; 1.5096x over previous
#include <cuda_runtime.h>
#include <cstdint>

// ---------------- static scratch (device globals: allocation-free) ----------------
#define NMAX 100000
#define EMAX 1600000
#define HDIM 64

__device__ float g_deg[NMAX];
__device__ float g_dis[NMAX];
__device__ int   g_src[EMAX];
__device__ int   g_tgt[EMAX];
__device__ int   g_rowcnt[NMAX];
__device__ int   g_rowptr[NMAX + 1];
__device__ int   g_cursor[NMAX];
__device__ int   g_bsum[128];
__device__ int   g_bsumoff[128];
__device__ int2  g_epay[EMAX];          // {src, bits(wn)} grouped by tgt
__device__ float g_bufA[(size_t)NMAX * HDIM];
__device__ float g_bufB[(size_t)NMAX * HDIM];
__device__ float g_tx1[(size_t)NMAX * HDIM];
__device__ float g_tmp[(size_t)NMAX * HDIM];
__device__ float g_weff[4 * 192 * 64];
__device__ float g_sums[64];
__device__ float g_cnt[64];

// ---------------- utility ----------------
__global__ void init_counts_kernel(int n) {
    int i = blockIdx.x * blockDim.x + threadIdx.x;
    if (i < n) { g_deg[i] = 0.f; g_rowcnt[i] = 0; }
}

__global__ void zero_pool_kernel() {
    int i = threadIdx.x;
    if (i < 64) g_sums[i] = 0.f;
    else if (i < 128) g_cnt[i - 64] = 0.f;
}

// ---------------- preprocessing ----------------
// edge_index is int32 (JAX default x64-disabled downcasts the reference's int64).
__global__ void edge_prep_kernel(const int* __restrict__ ei,
                                 const float* __restrict__ ew, int E, int N) {
    int e = blockIdx.x * blockDim.x + threadIdx.x;
    if (e >= E) return;
    int s = ei[e];
    int t = ei[(size_t)E + e];
    if ((unsigned)s >= (unsigned)N) s = 0;   // harden against dtype surprises
    if ((unsigned)t >= (unsigned)N) t = 0;
    g_src[e] = s;
    g_tgt[e] = t;
    atomicAdd(&g_deg[s], ew[e]);
    atomicAdd(&g_rowcnt[t], 1);
}

__global__ void dis_kernel(int n) {
    int i = blockIdx.x * blockDim.x + threadIdx.x;
    if (i >= n) return;
    float d = g_deg[i];
    g_dis[i] = (d > 0.f) ? rsqrtf(d) : 0.f;
}

// ---- multi-block exclusive scan of g_rowcnt -> g_rowptr (3 tiny kernels) ----
__global__ void scan_block_kernel(int N) {
    __shared__ int wsum[32];
    int tid = threadIdx.x, lane = tid & 31, wid = tid >> 5;
    int i = blockIdx.x * 1024 + tid;
    int v = (i < N) ? g_rowcnt[i] : 0;
    int s = v;
#pragma unroll
    for (int o = 1; o < 32; o <<= 1) {
        int u = __shfl_up_sync(0xffffffffu, s, o);
        if (lane >= o) s += u;
    }
    if (lane == 31) wsum[wid] = s;
    __syncthreads();
    if (tid < 32) {
        int s2 = wsum[tid];
#pragma unroll
        for (int o = 1; o < 32; o <<= 1) {
            int u = __shfl_up_sync(0xffffffffu, s2, o);
            if (tid >= o) s2 += u;
        }
        wsum[tid] = s2;
    }
    __syncthreads();
    int excl = (wid ? wsum[wid - 1] : 0) + (s - v);
    if (i < N) g_rowptr[i] = excl;           // block-local exclusive
    if (tid == 1023) g_bsum[blockIdx.x] = wsum[31];
}

__global__ void scan_bsum_kernel(int nb) {   // 1 block, 128 threads, nb <= 128
    __shared__ int ws[4];
    int tid = threadIdx.x, lane = tid & 31, wid = tid >> 5;
    int v = (tid < nb) ? g_bsum[tid] : 0;
    int s = v;
#pragma unroll
    for (int o = 1; o < 32; o <<= 1) {
        int u = __shfl_up_sync(0xffffffffu, s, o);
        if (lane >= o) s += u;
    }
    if (lane == 31) ws[wid] = s;
    __syncthreads();
    if (tid == 0) { int a = 0; for (int w = 0; w < 4; w++) { int t = ws[w]; ws[w] = a; a += t; } }
    __syncthreads();
    int excl = ws[wid] + (s - v);
    if (tid < nb) g_bsumoff[tid] = excl;
}

__global__ void scan_add_kernel(int N, int E) {
    int i = blockIdx.x * 1024 + threadIdx.x;
    if (i < N) {
        int r = g_rowptr[i] + g_bsumoff[blockIdx.x];
        g_rowptr[i] = r;
        g_cursor[i] = r;
    }
    if (blockIdx.x == 0 && threadIdx.x == 0) g_rowptr[N] = E;
}

// scatter edges into CSR slots; fuse wn computation
__global__ void fill_kernel(const float* __restrict__ ew, int E) {
    int e = blockIdx.x * blockDim.x + threadIdx.x;
    if (e >= E) return;
    int s = g_src[e];
    int t = g_tgt[e];
    float wn = -g_dis[s] * ew[e] * g_dis[t];
    int pos = atomicAdd(&g_cursor[t], 1);
    g_epay[pos] = make_int2(s, __float_as_int(wn));
}

// Weff[l][kk][o]: kk<64 -> W0-W2 ; 64..127 -> W1 ; 128..191 -> 2*W2
__global__ void weff_kernel(const float* __restrict__ w) {
    int idx = blockIdx.x * blockDim.x + threadIdx.x;
    if (idx >= 4 * 192 * 64) return;
    int o  = idx & 63;
    int kk = (idx >> 6) % 192;
    int l  = idx / (192 * 64);
    const float* wl = w + (size_t)l * 3 * 4096;
    float v;
    if (kk < 64)       v = wl[kk * 64 + o] - wl[2 * 4096 + kk * 64 + o];
    else if (kk < 128) v = wl[4096 + (kk - 64) * 64 + o];
    else               v = 2.f * wl[2 * 4096 + (kk - 128) * 64 + o];
    g_weff[idx] = v;
}

// ---------------- warp-per-node CSR propagation ----------------
// Warp owns one node; lane owns 8B (float2) of the 256B feature row.
// Payloads loaded 32-at-a-time (coalesced), broadcast via shuffle. No divergence.
__global__ void prop_warp_kernel(const float* __restrict__ h, float* __restrict__ out, int n) {
    int node = (blockIdx.x * blockDim.x + threadIdx.x) >> 5;
    if (node >= n) return;
    int lane = threadIdx.x & 31;
    int beg = g_rowptr[node];
    int end = g_rowptr[node + 1];
    const float2* __restrict__ hp = reinterpret_cast<const float2*>(h);
    float ax = 0.f, ay = 0.f;
    for (int j0 = beg; j0 < end; j0 += 32) {
        int jj = j0 + lane;
        int2 p = (jj < end) ? g_epay[jj] : make_int2(0, 0);
        int cnt = end - j0;
        if (cnt > 32) cnt = 32;
#pragma unroll 4
        for (int k = 0; k < cnt; k++) {
            int s   = __shfl_sync(0xffffffffu, p.x, k);
            float w = __int_as_float(__shfl_sync(0xffffffffu, p.y, k));
            float2 v = hp[(size_t)s * 32 + lane];
            ax += w * v.x;
            ay += w * v.y;
        }
    }
    reinterpret_cast<float2*>(out)[(size_t)node * 32 + lane] = make_float2(ax, ay);
}

// ---------------- fused layer GEMM: out = [p0|p1|p2] @ Weff + bias ----------------
// BM=128, BN=64, BK=8. 128 threads, each computes 8x8. 4 LDS.128 per 64 FMA.
__global__ void gemm_kernel(const float* __restrict__ p0, const float* __restrict__ p1,
                            const float* __restrict__ p2, const float* __restrict__ Weff,
                            const float* __restrict__ bias, float* __restrict__ out,
                            int n_nodes) {
    __shared__ float As[8][128];
    __shared__ float Bs[8][64];
    __shared__ float bsm[64];
    int tid = threadIdx.x;
    int m0 = blockIdx.x * 128;
    if (tid < 64) bsm[tid] = bias[tid];
    int tm = tid >> 3;          // 0..15
    int tn = tid & 7;           // 0..7
    float acc[8][8];
#pragma unroll
    for (int i = 0; i < 8; i++)
#pragma unroll
        for (int j = 0; j < 8; j++) acc[i][j] = 0.f;

    const float* parts[3] = {p0, p1, p2};
    int my_node = m0 + tid;
    bool a_ok = (my_node < n_nodes);

#pragma unroll 1
    for (int chunk = 0; chunk < 24; chunk++) {
        int kg = chunk * 8;
        const float* P = parts[kg >> 6];
        int ko = kg & 63;
        // A tile: thread t loads row (m0+t), k = ko..ko+7 (2x float4), store transposed
        float4 av0 = make_float4(0.f, 0.f, 0.f, 0.f);
        float4 av1 = make_float4(0.f, 0.f, 0.f, 0.f);
        if (a_ok) {
            const float* rp = P + (size_t)my_node * 64 + ko;
            av0 = *reinterpret_cast<const float4*>(rp);
            av1 = *reinterpret_cast<const float4*>(rp + 4);
        }
        As[0][tid] = av0.x; As[1][tid] = av0.y; As[2][tid] = av0.z; As[3][tid] = av0.w;
        As[4][tid] = av1.x; As[5][tid] = av1.y; As[6][tid] = av1.z; As[7][tid] = av1.w;
        // B tile: 8 rows x 64 cols
        {
            int kr = tid >> 4;           // 0..7
            int c4 = (tid & 15) << 2;    // 0..60
            float4 bv = *reinterpret_cast<const float4*>(Weff + (size_t)(kg + kr) * 64 + c4);
            *reinterpret_cast<float4*>(&Bs[kr][c4]) = bv;
        }
        __syncthreads();
#pragma unroll
        for (int k = 0; k < 8; k++) {
            float4 a0 = *reinterpret_cast<const float4*>(&As[k][tm << 3]);
            float4 a1 = *reinterpret_cast<const float4*>(&As[k][(tm << 3) + 4]);
            float4 b0 = *reinterpret_cast<const float4*>(&Bs[k][tn << 3]);
            float4 b1 = *reinterpret_cast<const float4*>(&Bs[k][(tn << 3) + 4]);
            float av[8] = {a0.x, a0.y, a0.z, a0.w, a1.x, a1.y, a1.z, a1.w};
            float bv[8] = {b0.x, b0.y, b0.z, b0.w, b1.x, b1.y, b1.z, b1.w};
#pragma unroll
            for (int i = 0; i < 8; i++)
#pragma unroll
                for (int j = 0; j < 8; j++)
                    acc[i][j] += av[i] * bv[j];
        }
        __syncthreads();
    }
    // epilogue: add bias, store
#pragma unroll
    for (int i = 0; i < 8; i++) {
        int node = m0 + (tm << 3) + i;
        if (node < n_nodes) {
            int n0 = tn << 3;
            float4 o0, o1;
            o0.x = acc[i][0] + bsm[n0 + 0];
            o0.y = acc[i][1] + bsm[n0 + 1];
            o0.z = acc[i][2] + bsm[n0 + 2];
            o0.w = acc[i][3] + bsm[n0 + 3];
            o1.x = acc[i][4] + bsm[n0 + 4];
            o1.y = acc[i][5] + bsm[n0 + 5];
            o1.z = acc[i][6] + bsm[n0 + 6];
            o1.w = acc[i][7] + bsm[n0 + 7];
            float* op = out + (size_t)node * 64 + n0;
            *reinterpret_cast<float4*>(op) = o0;
            *reinterpret_cast<float4*>(op + 4) = o1;
        }
    }
}

// ---------------- readout MLP (64->32 relu ->1) + scatter mean ----------------
__global__ void readout_kernel(const float* __restrict__ y, const int* __restrict__ batch,
                               const float* __restrict__ wr1, const float* __restrict__ br1,
                               const float* __restrict__ wr2, const float* __restrict__ br2,
                               int n, int G) {
    __shared__ float Wsm[64 * 32];
    __shared__ float w2sm[32];
    __shared__ float b1sm[32];
    for (int i = threadIdx.x; i < 64 * 32; i += blockDim.x) Wsm[i] = wr1[i];
    if (threadIdx.x < 32) {
        w2sm[threadIdx.x] = wr2[threadIdx.x];
        b1sm[threadIdx.x] = br1[threadIdx.x];
    }
    __syncthreads();
    float b2 = br2[0];
    int lane = threadIdx.x & 31;
    int warp = (blockIdx.x * blockDim.x + threadIdx.x) >> 5;
    int nwarps = (gridDim.x * blockDim.x) >> 5;
    for (int node = warp; node < n; node += nwarps) {
        float yv0 = y[(size_t)node * 64 + lane];
        float yv1 = y[(size_t)node * 64 + 32 + lane];
        float acc = b1sm[lane];
#pragma unroll
        for (int k = 0; k < 32; k++)
            acc += __shfl_sync(0xffffffffu, yv0, k) * Wsm[k * 32 + lane];
#pragma unroll
        for (int k = 0; k < 32; k++)
            acc += __shfl_sync(0xffffffffu, yv1, k) * Wsm[(32 + k) * 32 + lane];
        acc = fmaxf(acc, 0.f);
        float r = acc * w2sm[lane];
#pragma unroll
        for (int off = 16; off; off >>= 1)
            r += __shfl_xor_sync(0xffffffffu, r, off);
        if (lane == 0) {
            int g = batch[node];
            if ((unsigned)g < (unsigned)G) {
                atomicAdd(&g_sums[g], r + b2);
                atomicAdd(&g_cnt[g], 1.f);
            }
        }
    }
}

__global__ void finalize_kernel(float* __restrict__ out, int G) {
    int g = threadIdx.x;
    if (g < G) out[g] = g_sums[g] / fmaxf(g_cnt[g], 1.f);
}

// ---------------- host ----------------
extern "C" void kernel_launch(void* const* d_in, const int* in_sizes, int n_in,
                              void* d_out, int out_size) {
    const float* x        = (const float*)d_in[0];
    const int*   ei       = (const int*)d_in[1];     // int32 (JAX x64 disabled)
    const float* ew       = (const float*)d_in[2];
    const int*   batch    = (const int*)d_in[3];     // int32
    const float* w_layers = (const float*)d_in[4];
    const float* b_layers = (const float*)d_in[5];
    const float* wr1      = (const float*)d_in[6];
    const float* br1      = (const float*)d_in[7];
    const float* wr2      = (const float*)d_in[8];
    const float* br2      = (const float*)d_in[9];

    int N = in_sizes[0] / HDIM;
    int E = in_sizes[1] / 2;
    int G = out_size;

    float *bufA, *bufB, *tx1, *tmp, *weff;
    cudaGetSymbolAddress((void**)&bufA, g_bufA);
    cudaGetSymbolAddress((void**)&bufB, g_bufB);
    cudaGetSymbolAddress((void**)&tx1,  g_tx1);
    cudaGetSymbolAddress((void**)&tmp,  g_tmp);
    cudaGetSymbolAddress((void**)&weff, g_weff);

    const int TPB = 256;
    int nb = (N + 1023) / 1024;          // scan blocks (<=128)

    // preprocessing: degrees + CSR by target
    init_counts_kernel<<<(N + TPB - 1) / TPB, TPB>>>(N);
    edge_prep_kernel<<<(E + TPB - 1) / TPB, TPB>>>(ei, ew, E, N);
    dis_kernel<<<(N + TPB - 1) / TPB, TPB>>>(N);
    scan_block_kernel<<<nb, 1024>>>(N);
    scan_bsum_kernel<<<1, 128>>>(nb);
    scan_add_kernel<<<nb, 1024>>>(N, E);
    fill_kernel<<<(E + TPB - 1) / TPB, TPB>>>(ew, E);
    weff_kernel<<<(4 * 192 * 64 + TPB - 1) / TPB, TPB>>>(w_layers);

    int pgrid = (int)(((long long)N * 32 + TPB - 1) / TPB);
    int ggrid = (N + 127) / 128;

    const float* ycur = x;
    float* bufs[2] = {bufA, bufB};
    for (int l = 0; l < 4; l++) {
        prop_warp_kernel<<<pgrid, TPB>>>(ycur, tx1, N);
        prop_warp_kernel<<<pgrid, TPB>>>(tx1, tmp, N);
        gemm_kernel<<<ggrid, TPB / 2>>>(ycur, tx1, tmp,
                                        weff + (size_t)l * 192 * 64,
                                        b_layers + (size_t)l * 64,
                                        bufs[l & 1], N);
        ycur = bufs[l & 1];
    }

    // readout + pooling
    zero_pool_kernel<<<1, 128>>>();
    readout_kernel<<<256, TPB>>>(ycur, batch, wr1, br1, wr2, br2, N, G);
    finalize_kernel<<<1, 64>>>((float*)d_out, G);
}